// round 6
// baseline (speedup 1.0000x reference)
#include <cuda_runtime.h>
#include <cstdint>

#define NTPL 10
#define NACC 11                                   // 10 cross + 1 x·x
#define PIX 784
#define IMG_BYTES 3136                            // PIX*4
#define TILE 128                                  // images per logical tile
#define NGRP 4                                    // 4 groups of 32 images
#define CHUNKS 196                                // float4 chunks per image
#define QCHUNKS 49                                // chunks per quarter-stage
#define NW 12                                     // warps
#define THREADS (NW * 32)                         // 384
#define QROW 784                                  // bytes per image-quarter row
#define STAGE_BYTES (TILE * QROW)                 // 100352; stride 196w == 4 mod 32 -> conflict-free
#define TM_OFF (2 * STAGE_BYTES)                  // 200704 templates [k][chunk] 16B
#define MBAR0 (TM_OFF + NTPL * PIX * 4)           // 232064
#define MBAR1 (MBAR0 + 16)
#define TSQ_OFF (MBAR0 + 32)                      // 10 doubles
#define SMEM_TOTAL (MBAR0 + 112)                  // 232176 <= 232448

#define FMA2(acc, a, b) \
    asm("fma.rn.f32x2 %0, %1, %2, %0;" : "+l"(acc) : "l"(a), "l"(b))

__device__ __forceinline__ void mbar_wait(uint32_t addr, uint32_t phase) {
    uint32_t done = 0;
    while (!done) {
        asm volatile(
            "{\n\t.reg .pred p;\n\t"
            "mbarrier.try_wait.parity.acquire.cta.shared::cta.b64 p, [%1], %2, 0x989680;\n\t"
            "selp.b32 %0, 1, 0, p;\n\t}"
            : "=r"(done) : "r"(addr), "r"(phase) : "memory");
    }
}

// One thread: fetch quarter q of a 128-image tile (128 strided 784B rows).
__device__ __forceinline__ void fetch_quarter(int tile, int q, uint32_t sbase,
                                              uint32_t mbar, const char* __restrict__ xg) {
    asm volatile("mbarrier.arrive.expect_tx.shared.b64 _, [%0], %1;"
                 :: "r"(mbar), "r"((uint32_t)STAGE_BYTES) : "memory");
    const char* src = xg + (size_t)tile * (TILE * (size_t)IMG_BYTES) + (size_t)q * QROW;
    #pragma unroll 4
    for (int i = 0; i < TILE; i++) {
        asm volatile(
            "cp.async.bulk.shared::cta.global.mbarrier::complete_tx::bytes "
            "[%0], [%1], %2, [%3];"
            :: "r"(sbase + (uint32_t)(i * QROW)), "l"(src + (size_t)i * IMG_BYTES),
               "r"((uint32_t)QROW), "r"(mbar) : "memory");
    }
}

__global__ void __launch_bounds__(THREADS, 1)
mse_argmin_kernel(const float* __restrict__ xg, const float* __restrict__ tg,
                  float* __restrict__ out, int ntiles) {
    extern __shared__ float sm[];
    const uint32_t smb = (uint32_t)__cvta_generic_to_shared(sm);
    const int tid = threadIdx.x;
    const int w = tid >> 5;
    const int lane = tid & 31;
    const int G = gridDim.x;
    const int t0 = blockIdx.x;
    const char* xgc = (const char*)xg;
    const double INV784 = 1.0 / 784.0;

    if (tid == 0) {
        asm volatile("mbarrier.init.shared.b64 [%0], 1;" :: "r"(smb + MBAR0) : "memory");
        asm volatile("mbarrier.init.shared.b64 [%0], 1;" :: "r"(smb + MBAR1) : "memory");
        asm volatile("fence.proxy.async;" ::: "memory");
    }
    __syncthreads();

    const int nt_blk = (t0 < ntiles) ? (ntiles - t0 + G - 1) / G : 0;
    const int nq = nt_blk * 4;                    // linear quarter count for this block

    // Prologue: quarters j=0,1 of first tile.
    if (tid == 0 && nq > 0) {
        fetch_quarter(t0, 0, smb + 0u, smb + MBAR0, xgc);
        fetch_quarter(t0, 1, smb + STAGE_BYTES, smb + MBAR1, xgc);
    }

    // Templates -> smem [k][chunk] 16B granules.
    {
        const float4* tg4 = (const float4*)tg;
        float4* tm4 = (float4*)(sm + (TM_OFF >> 2));
        for (int i = tid; i < NTPL * CHUNKS; i += THREADS) tm4[i] = tg4[i];
    }
    // Exact (fp64) squared template norms (one warp per template).
    double* tsq_d = (double*)((char*)sm + TSQ_OFF);
    if (w < NTPL) {
        const float* tp = tg + w * PIX;
        double a = 0.0;
        for (int p = lane; p < PIX; p += 32) a = fma((double)tp[p], (double)tp[p], a);
        #pragma unroll
        for (int s = 16; s > 0; s >>= 1) a += __shfl_xor_sync(0xffffffffu, a, s);
        if (lane == 0) tsq_d[w] = a;
    }
    __syncthreads();

    uint64_t acc[NACC][NGRP];
    uint32_t ph[2] = {0, 0};

    for (int j = 0; j < nq; j++) {
        const int tile = t0 + (j >> 2) * G;
        const int q = j & 3;
        const int st = j & 1;
        const uint32_t sbase = smb + (st ? (uint32_t)STAGE_BYTES : 0u);
        const uint32_t mbar = smb + (st ? MBAR1 : MBAR0);

        mbar_wait(mbar, ph[st]);
        ph[st] ^= 1;

        if (q == 0) {
            #pragma unroll
            for (int k = 0; k < NACC; k++)
                #pragma unroll
                for (int g = 0; g < NGRP; g++) acc[k][g] = 0ull;
        }

        // Warp w owns global chunks c == w (mod NW); within quarter q those sit
        // at c_local == (w - q) mod 12 (49 = 4*12 + 1), preserving chain order.
        const int r = (w - q + 12) % NW;
        const int niter = (QCHUNKS - r + NW - 1) / NW;
        uint32_t xb = sbase + (uint32_t)lane * QROW + (uint32_t)r * 16u;
        uint32_t tb = smb + TM_OFF + (uint32_t)((q * QCHUNKS + r) * 16);
        #pragma unroll 1
        for (int i = 0; i < niter; i++) {
            uint64_t x01[NGRP], x23[NGRP];
            #pragma unroll
            for (int g = 0; g < NGRP; g++) {
                asm("ld.shared.v2.u64 {%0, %1}, [%2];"
                    : "=l"(x01[g]), "=l"(x23[g])
                    : "r"(xb + (uint32_t)(g * 32 * QROW)));
            }
            #pragma unroll
            for (int k = 0; k < NTPL; k++) {
                uint64_t a01, a23;
                asm("ld.shared.v2.u64 {%0, %1}, [%2];"
                    : "=l"(a01), "=l"(a23) : "r"(tb + (uint32_t)(k * CHUNKS * 16)));
                #pragma unroll
                for (int g = 0; g < NGRP; g++) {
                    FMA2(acc[k][g], x01[g], a01);
                    FMA2(acc[k][g], x23[g], a23);
                }
            }
            #pragma unroll
            for (int g = 0; g < NGRP; g++) {
                FMA2(acc[NTPL][g], x01[g], x01[g]);   // x·x
                FMA2(acc[NTPL][g], x23[g], x23[g]);
            }
            xb += (uint32_t)(NW * 16);
            tb += (uint32_t)(NW * 16);
        }
        __syncthreads();   // stage consumed

        if (q == 3) {
            // ---- epilogue in the dead stage (scratch) ----
            float* red = sm + (st ? (STAGE_BYTES >> 2) : 0);   // [k][w][img]
            #pragma unroll
            for (int k = 0; k < NACC; k++)
                #pragma unroll
                for (int g = 0; g < NGRP; g++) {
                    uint32_t lo, hi;
                    asm("mov.b64 {%0, %1}, %2;" : "=r"(lo), "=r"(hi) : "l"(acc[k][g]));
                    red[(k * NW + w) * TILE + g * 32 + lane] =
                        __uint_as_float(lo) + __uint_as_float(hi);
                }
            __syncthreads();

            // Exact 12-way fold via fp32 TwoSum cascade -> fp64 value per (k,img).
            double* cd = (double*)((char*)red + 68608);        // [k][img], k=10 is x·x
            for (int p = tid; p < NACC * TILE; p += THREADS) {
                const int k = p / TILE, img = p % TILE;
                const float* rp = red + k * (NW * TILE) + img;
                float fs = 0.f, fe = 0.f;
                #pragma unroll
                for (int ww = 0; ww < NW; ww++) {
                    const float v = rp[ww * TILE];
                    const float tt = fs + v;
                    const float z = tt - fs;
                    fe += (fs - (tt - z)) + (v - z);
                    fs = tt;
                }
                cd[p] = (double)fs + (double)fe;
            }
            __syncthreads();

            // Distances in fp64, rounded to fp32 exactly like the reference.
            float* df = (float*)((char*)red + 68608 + NACC * TILE * 8);  // [k][img]
            for (int p = tid; p < NTPL * TILE; p += THREADS) {
                const int img = p % TILE;
                const double v = (fma(-2.0, cd[p], cd[NTPL * TILE + img])
                                  + tsq_d[p / TILE]) * INV784;
                df[p] = (float)v;
            }
            __syncthreads();

            // argmin (strict <, first index wins ties == jnp.argmin).
            if (tid < TILE) {
                float best = df[tid];
                int bi = 0;
                #pragma unroll
                for (int kk = 1; kk < NTPL; kk++) {
                    const float v = df[kk * TILE + tid];
                    if (v < best) { best = v; bi = kk; }
                }
                out[(size_t)tile * TILE + tid] = (float)bi;
            }
            __syncthreads();
        }

        // Refill this stage with linear quarter j+2.
        if (tid == 0 && j + 2 < nq) {
            const int j2 = j + 2;
            fetch_quarter(t0 + (j2 >> 2) * G, j2 & 3, sbase, mbar, xgc);
        }
    }
}

extern "C" void kernel_launch(void* const* d_in, const int* in_sizes, int n_in,
                              void* d_out, int out_size) {
    // Robust to input ordering: x is the big one.
    const float* a = (const float*)d_in[0];
    const float* b = (const float*)d_in[1];
    const float* xg;
    const float* tg;
    long nx;
    if (in_sizes[0] >= in_sizes[1]) { xg = a; tg = b; nx = in_sizes[0]; }
    else                            { xg = b; tg = a; nx = in_sizes[1]; }

    const int B = (int)(nx / PIX);
    const int ntiles = B / TILE;   // 262144/128 = 2048, exact

    int dev = 0;
    cudaGetDevice(&dev);
    int nsm = 148;
    cudaDeviceGetAttribute(&nsm, cudaDevAttrMultiProcessorCount, dev);
    int grid = nsm < ntiles ? nsm : ntiles;

    cudaFuncSetAttribute(mse_argmin_kernel,
                         cudaFuncAttributeMaxDynamicSharedMemorySize, SMEM_TOTAL);

    mse_argmin_kernel<<<grid, THREADS, SMEM_TOTAL>>>(xg, tg, (float*)d_out, ntiles);
}

// round 7
// speedup vs baseline: 1.6884x; 1.6884x over previous
#include <cuda_runtime.h>
#include <cuda.h>
#include <cstdint>

#define NTPL 10
#define NACC 11                                   // 10 cross + 1 x·x
#define PIX 784
#define IMG_BYTES 3136                            // PIX*4
#define TILE 128                                  // images per logical tile
#define NGRP 4                                    // 4 groups of 32 images
#define CHUNKS 196                                // float4 chunks per image
#define QCHUNKS 49                                // chunks per quarter-stage
#define NW 12                                     // warps
#define THREADS (NW * 32)                         // 384
#define QROW 784                                  // bytes per image-quarter row
#define STAGE_BYTES (TILE * QROW)                 // 100352; 196w == 4 mod 32 -> conflict-free
#define TM_OFF (2 * STAGE_BYTES)                  // 200704 templates [k][chunk] 16B
#define MBAR0 (TM_OFF + NTPL * PIX * 4)           // 232064
#define MBAR1 (MBAR0 + 16)
#define TSQ_OFF (MBAR0 + 32)                      // 10 doubles
#define SMEM_TOTAL (MBAR0 + 112)                  // 232176 <= 232448

#define FMA2(acc, a, b) \
    asm("fma.rn.f32x2 %0, %1, %2, %0;" : "+l"(acc) : "l"(a), "l"(b))

__device__ __forceinline__ void mbar_wait(uint32_t addr, uint32_t phase) {
    uint32_t done = 0;
    while (!done) {
        asm volatile(
            "{\n\t.reg .pred p;\n\t"
            "mbarrier.try_wait.parity.acquire.cta.shared::cta.b64 p, [%1], %2, 0x989680;\n\t"
            "selp.b32 %0, 1, 0, p;\n\t}"
            : "=r"(done) : "r"(addr), "r"(phase) : "memory");
    }
}

// One thread: fetch quarter q of a 128-image tile with a SINGLE 2D TMA request.
__device__ __forceinline__ void fetch_quarter(const CUtensorMap* tmap, int tile, int q,
                                              uint32_t sbase, uint32_t mbar) {
    asm volatile("mbarrier.arrive.expect_tx.shared.b64 _, [%0], %1;"
                 :: "r"(mbar), "r"((uint32_t)STAGE_BYTES) : "memory");
    const int cx = q * QCHUNKS * 4;               // element (fp32) coordinate
    const int cy = tile * TILE;                   // image row coordinate
    asm volatile(
        "cp.async.bulk.tensor.2d.shared::cta.global.tile.mbarrier::complete_tx::bytes "
        "[%0], [%1, {%2, %3}], [%4];"
        :: "r"(sbase), "l"(tmap), "r"(cx), "r"(cy), "r"(mbar) : "memory");
}

__global__ void __launch_bounds__(THREADS, 1)
mse_argmin_kernel(const __grid_constant__ CUtensorMap tmap,
                  const float* __restrict__ tg, float* __restrict__ out, int ntiles) {
    extern __shared__ float sm[];
    const uint32_t smb = (uint32_t)__cvta_generic_to_shared(sm);
    const int tid = threadIdx.x;
    const int w = tid >> 5;
    const int lane = tid & 31;
    const int G = gridDim.x;
    const int t0 = blockIdx.x;
    const double INV784 = 1.0 / 784.0;

    if (tid == 0) {
        asm volatile("prefetch.tensormap [%0];" :: "l"(&tmap));
        asm volatile("mbarrier.init.shared.b64 [%0], 1;" :: "r"(smb + MBAR0) : "memory");
        asm volatile("mbarrier.init.shared.b64 [%0], 1;" :: "r"(smb + MBAR1) : "memory");
        asm volatile("fence.proxy.async;" ::: "memory");
    }
    __syncthreads();

    const int nt_blk = (t0 < ntiles) ? (ntiles - t0 + G - 1) / G : 0;
    const int nq = nt_blk * 4;                    // linear quarter count for this block

    // Prologue: quarters j=0,1 of first tile.
    if (tid == 0 && nq > 0) {
        fetch_quarter(&tmap, t0, 0, smb + 0u, smb + MBAR0);
        fetch_quarter(&tmap, t0, 1, smb + STAGE_BYTES, smb + MBAR1);
    }

    // Templates -> smem [k][chunk] 16B granules.
    {
        const float4* tg4 = (const float4*)tg;
        float4* tm4 = (float4*)(sm + (TM_OFF >> 2));
        for (int i = tid; i < NTPL * CHUNKS; i += THREADS) tm4[i] = tg4[i];
    }
    // Exact (fp64) squared template norms (one warp per template).
    double* tsq_d = (double*)((char*)sm + TSQ_OFF);
    if (w < NTPL) {
        const float* tp = tg + w * PIX;
        double a = 0.0;
        for (int p = lane; p < PIX; p += 32) a = fma((double)tp[p], (double)tp[p], a);
        #pragma unroll
        for (int s = 16; s > 0; s >>= 1) a += __shfl_xor_sync(0xffffffffu, a, s);
        if (lane == 0) tsq_d[w] = a;
    }
    __syncthreads();

    uint64_t acc[NACC][NGRP];
    uint32_t ph[2] = {0, 0};

    for (int j = 0; j < nq; j++) {
        const int tile = t0 + (j >> 2) * G;
        const int q = j & 3;
        const int st = j & 1;
        const uint32_t sbase = smb + (st ? (uint32_t)STAGE_BYTES : 0u);
        const uint32_t mbar = smb + (st ? MBAR1 : MBAR0);

        mbar_wait(mbar, ph[st]);
        ph[st] ^= 1;

        if (q == 0) {
            #pragma unroll
            for (int k = 0; k < NACC; k++)
                #pragma unroll
                for (int g = 0; g < NGRP; g++) acc[k][g] = 0ull;
        }

        // Warp w owns global chunks c == w (mod NW); within quarter q those sit
        // at c_local == (w - q) mod 12 (49 = 4*12 + 1), preserving chain order.
        const int r = (w - q + 12) % NW;
        const int niter = (QCHUNKS - r + NW - 1) / NW;
        uint32_t xb = sbase + (uint32_t)lane * QROW + (uint32_t)r * 16u;
        uint32_t tb = smb + TM_OFF + (uint32_t)((q * QCHUNKS + r) * 16);
        #pragma unroll 2
        for (int i = 0; i < niter; i++) {
            uint64_t x01[NGRP], x23[NGRP];
            #pragma unroll
            for (int g = 0; g < NGRP; g++) {
                asm("ld.shared.v2.u64 {%0, %1}, [%2];"
                    : "=l"(x01[g]), "=l"(x23[g])
                    : "r"(xb + (uint32_t)(g * 32 * QROW)));
            }
            #pragma unroll
            for (int k = 0; k < NTPL; k++) {
                uint64_t a01, a23;
                asm("ld.shared.v2.u64 {%0, %1}, [%2];"
                    : "=l"(a01), "=l"(a23) : "r"(tb + (uint32_t)(k * CHUNKS * 16)));
                #pragma unroll
                for (int g = 0; g < NGRP; g++) {
                    FMA2(acc[k][g], x01[g], a01);
                    FMA2(acc[k][g], x23[g], a23);
                }
            }
            #pragma unroll
            for (int g = 0; g < NGRP; g++) {
                FMA2(acc[NTPL][g], x01[g], x01[g]);   // x·x
                FMA2(acc[NTPL][g], x23[g], x23[g]);
            }
            xb += (uint32_t)(NW * 16);
            tb += (uint32_t)(NW * 16);
        }
        __syncthreads();   // stage consumed

        if (q == 3) {
            // ---- epilogue in the dead stage (scratch) ----
            float* red = sm + (st ? (STAGE_BYTES >> 2) : 0);   // [k][w][img]
            #pragma unroll
            for (int k = 0; k < NACC; k++)
                #pragma unroll
                for (int g = 0; g < NGRP; g++) {
                    uint32_t lo, hi;
                    asm("mov.b64 {%0, %1}, %2;" : "=r"(lo), "=r"(hi) : "l"(acc[k][g]));
                    red[(k * NW + w) * TILE + g * 32 + lane] =
                        __uint_as_float(lo) + __uint_as_float(hi);
                }
            __syncthreads();

            // Exact 12-way fold via fp32 TwoSum cascade -> fp64 value per (k,img).
            double* cd = (double*)((char*)red + 68608);        // [k][img], k=10 is x·x
            for (int p = tid; p < NACC * TILE; p += THREADS) {
                const int k = p / TILE, img = p % TILE;
                const float* rp = red + k * (NW * TILE) + img;
                float fs = 0.f, fe = 0.f;
                #pragma unroll
                for (int ww = 0; ww < NW; ww++) {
                    const float v = rp[ww * TILE];
                    const float tt = fs + v;
                    const float z = tt - fs;
                    fe += (fs - (tt - z)) + (v - z);
                    fs = tt;
                }
                cd[p] = (double)fs + (double)fe;
            }
            __syncthreads();

            // Distances in fp64, rounded to fp32 exactly like the reference.
            float* df = (float*)((char*)red + 68608 + NACC * TILE * 8);  // [k][img]
            for (int p = tid; p < NTPL * TILE; p += THREADS) {
                const int img = p % TILE;
                const double v = (fma(-2.0, cd[p], cd[NTPL * TILE + img])
                                  + tsq_d[p / TILE]) * INV784;
                df[p] = (float)v;
            }
            __syncthreads();

            // argmin (strict <, first index wins ties == jnp.argmin).
            if (tid < TILE) {
                float best = df[tid];
                int bi = 0;
                #pragma unroll
                for (int kk = 1; kk < NTPL; kk++) {
                    const float v = df[kk * TILE + tid];
                    if (v < best) { best = v; bi = kk; }
                }
                out[(size_t)tile * TILE + tid] = (float)bi;
            }
            __syncthreads();
        }

        // Refill this stage with linear quarter j+2 (one TMA request).
        if (tid == 0 && j + 2 < nq) {
            const int j2 = j + 2;
            fetch_quarter(&tmap, t0 + (j2 >> 2) * G, j2 & 3, sbase, mbar);
        }
    }
}

typedef CUresult (*EncodeFn)(CUtensorMap*, CUtensorMapDataType, cuuint32_t, void*,
                             const cuuint64_t*, const cuuint64_t*, const cuuint32_t*,
                             const cuuint32_t*, CUtensorMapInterleave, CUtensorMapSwizzle,
                             CUtensorMapL2promotion, CUtensorMapFloatOOBfill);

extern "C" void kernel_launch(void* const* d_in, const int* in_sizes, int n_in,
                              void* d_out, int out_size) {
    // Robust to input ordering: x is the big one.
    const float* a = (const float*)d_in[0];
    const float* b = (const float*)d_in[1];
    const float* xg;
    const float* tg;
    long nx;
    if (in_sizes[0] >= in_sizes[1]) { xg = a; tg = b; nx = in_sizes[0]; }
    else                            { xg = b; tg = a; nx = in_sizes[1]; }

    const int B = (int)(nx / PIX);
    const int ntiles = B / TILE;   // 262144/128 = 2048, exact

    // Encode the x tensormap: [784 cols x B rows] fp32, box [196 x 128].
    static CUtensorMap tmap;       // persists across graph replays
    {
        EncodeFn enc = nullptr;
        cudaDriverEntryPointQueryResult qr;
        cudaGetDriverEntryPointByVersion("cuTensorMapEncodeTiled", (void**)&enc,
                                         12000, cudaEnableDefault, &qr);
        cuuint64_t gdims[2] = {(cuuint64_t)PIX, (cuuint64_t)B};
        cuuint64_t gstride[1] = {(cuuint64_t)IMG_BYTES};
        cuuint32_t box[2] = {(cuuint32_t)(QCHUNKS * 4), (cuuint32_t)TILE};
        cuuint32_t estride[2] = {1, 1};
        enc(&tmap, CU_TENSOR_MAP_DATA_TYPE_FLOAT32, 2, (void*)xg,
            gdims, gstride, box, estride,
            CU_TENSOR_MAP_INTERLEAVE_NONE, CU_TENSOR_MAP_SWIZZLE_NONE,
            CU_TENSOR_MAP_L2_PROMOTION_L2_128B, CU_TENSOR_MAP_FLOAT_OOB_FILL_NONE);
    }

    int dev = 0;
    cudaGetDevice(&dev);
    int nsm = 148;
    cudaDeviceGetAttribute(&nsm, cudaDevAttrMultiProcessorCount, dev);
    int grid = nsm < ntiles ? nsm : ntiles;

    cudaFuncSetAttribute(mse_argmin_kernel,
                         cudaFuncAttributeMaxDynamicSharedMemorySize, SMEM_TOTAL);

    mse_argmin_kernel<<<grid, THREADS, SMEM_TOTAL>>>(tmap, tg, (float*)d_out, ntiles);
}

// round 9
// speedup vs baseline: 1.6939x; 1.0033x over previous
#include <cuda_runtime.h>
#include <cuda.h>
#include <cstdint>

#define NTPL 10
#define NACC 11                                   // 10 cross + 1 x·x
#define PIX 784
#define IMG_BYTES 3136                            // PIX*4
#define TILE 128                                  // images per logical tile
#define NGRP 4                                    // 4 groups of 32 images
#define CHUNKS 196                                // float4 chunks per image
#define QCHUNKS 49                                // chunks per quarter-stage
#define NW 16                                     // warps
#define THREADS (NW * 32)                         // 512
#define QROW 784                                  // bytes per image-quarter row
#define STAGE_BYTES (TILE * QROW)                 // 100352; 196w == 4 mod 32 -> conflict-free
#define TM_OFF (2 * STAGE_BYTES)                  // 200704 templates [k][chunk] 16B
#define MBAR0 (TM_OFF + NTPL * PIX * 4)           // 232064
#define MBAR1 (MBAR0 + 16)
#define TSQ_OFF (MBAR0 + 32)                      // 10 doubles
#define SMEM_TOTAL (MBAR0 + 112)                  // 232176 <= 232448

#define RED_BYTES (NACC * NW * TILE * 4)          // 90112 (fits in one stage)
#define XXD_OFF_E RED_BYTES                       // 128 doubles = 1024 B
#define DF_OFF_E (RED_BYTES + 1024)               // 10*128 floats = 5120 B -> 96256 <= 100352

#define FMA2(acc, a, b) \
    asm("fma.rn.f32x2 %0, %1, %2, %0;" : "+l"(acc) : "l"(a), "l"(b))

// Immediate-offset shared loads: no address registers, no per-k IADD.
#define XLOAD(g, OFF) \
    asm("ld.shared.v2.u64 {%0, %1}, [%2+" OFF "];" \
        : "=l"(x01[g]), "=l"(x23[g]) : "r"(xb))

#define KSTEP(k, OFF) do { \
    uint64_t a01, a23; \
    asm("ld.shared.v2.u64 {%0, %1}, [%2+" OFF "];" \
        : "=l"(a01), "=l"(a23) : "r"(tb)); \
    FMA2(acc[k][0], x01[0], a01); FMA2(acc[k][0], x23[0], a23); \
    FMA2(acc[k][1], x01[1], a01); FMA2(acc[k][1], x23[1], a23); \
    FMA2(acc[k][2], x01[2], a01); FMA2(acc[k][2], x23[2], a23); \
    FMA2(acc[k][3], x01[3], a01); FMA2(acc[k][3], x23[3], a23); \
} while (0)

__device__ __forceinline__ void mbar_wait(uint32_t addr, uint32_t phase) {
    uint32_t done = 0;
    while (!done) {
        asm volatile(
            "{\n\t.reg .pred p;\n\t"
            "mbarrier.try_wait.parity.acquire.cta.shared::cta.b64 p, [%1], %2, 0x989680;\n\t"
            "selp.b32 %0, 1, 0, p;\n\t}"
            : "=r"(done) : "r"(addr), "r"(phase) : "memory");
    }
}

// One thread: fetch quarter q of a 128-image tile with a SINGLE 2D TMA request.
__device__ __forceinline__ void fetch_quarter(const CUtensorMap* tmap, int tile, int q,
                                              uint32_t sbase, uint32_t mbar) {
    asm volatile("mbarrier.arrive.expect_tx.shared.b64 _, [%0], %1;"
                 :: "r"(mbar), "r"((uint32_t)STAGE_BYTES) : "memory");
    const int cx = q * QCHUNKS * 4;               // element (fp32) coordinate
    const int cy = tile * TILE;                   // image row coordinate
    asm volatile(
        "cp.async.bulk.tensor.2d.shared::cta.global.tile.mbarrier::complete_tx::bytes "
        "[%0], [%1, {%2, %3}], [%4];"
        :: "r"(sbase), "l"(tmap), "r"(cx), "r"(cy), "r"(mbar) : "memory");
}

__global__ void __launch_bounds__(THREADS, 1)
mse_argmin_kernel(const __grid_constant__ CUtensorMap tmap,
                  const float* __restrict__ tg, float* __restrict__ out, int ntiles) {
    extern __shared__ float sm[];
    const uint32_t smb = (uint32_t)__cvta_generic_to_shared(sm);
    const int tid = threadIdx.x;
    const int w = tid >> 5;
    const int lane = tid & 31;
    const int G = gridDim.x;
    const int t0 = blockIdx.x;
    const double INV784 = 1.0 / 784.0;

    if (tid == 0) {
        asm volatile("prefetch.tensormap [%0];" :: "l"(&tmap));
        asm volatile("mbarrier.init.shared.b64 [%0], 1;" :: "r"(smb + MBAR0) : "memory");
        asm volatile("mbarrier.init.shared.b64 [%0], 1;" :: "r"(smb + MBAR1) : "memory");
        asm volatile("fence.proxy.async;" ::: "memory");
    }
    __syncthreads();

    const int nt_blk = (t0 < ntiles) ? (ntiles - t0 + G - 1) / G : 0;
    const int nq = nt_blk * 4;                    // linear quarter count for this block

    // Prologue: quarters j=0,1 of first tile.
    if (tid == 0 && nq > 0) {
        fetch_quarter(&tmap, t0, 0, smb + 0u, smb + MBAR0);
        fetch_quarter(&tmap, t0, 1, smb + STAGE_BYTES, smb + MBAR1);
    }

    // Templates -> smem [k][chunk] 16B granules.
    {
        const float4* tg4 = (const float4*)tg;
        float4* tm4 = (float4*)(sm + (TM_OFF >> 2));
        for (int i = tid; i < NTPL * CHUNKS; i += THREADS) tm4[i] = tg4[i];
    }
    // Exact (fp64) squared template norms (one warp per template).
    double* tsq_d = (double*)((char*)sm + TSQ_OFF);
    if (w < NTPL) {
        const float* tp = tg + w * PIX;
        double a = 0.0;
        for (int p = lane; p < PIX; p += 32) a = fma((double)tp[p], (double)tp[p], a);
        #pragma unroll
        for (int s = 16; s > 0; s >>= 1) a += __shfl_xor_sync(0xffffffffu, a, s);
        if (lane == 0) tsq_d[w] = a;
    }
    __syncthreads();

    uint64_t acc[NACC][NGRP];
    uint32_t ph[2] = {0, 0};

    for (int j = 0; j < nq; j++) {
        const int tile = t0 + (j >> 2) * G;
        const int q = j & 3;
        const int st = j & 1;
        const uint32_t sbase = smb + (st ? (uint32_t)STAGE_BYTES : 0u);
        const uint32_t mbar = smb + (st ? MBAR1 : MBAR0);

        mbar_wait(mbar, ph[st]);
        ph[st] ^= 1;

        if (q == 0) {
            #pragma unroll
            for (int k = 0; k < NACC; k++)
                #pragma unroll
                for (int g = 0; g < NGRP; g++) acc[k][g] = 0ull;
        }

        // Warp w owns global chunks c == w (mod NW); 49 == 1 (mod 16), so within
        // quarter q they sit at c_local == (w - q) mod 16, preserving chain order.
        const int r = (w - q + NW) & (NW - 1);
        const int niter = (QCHUNKS - r + NW - 1) / NW;
        uint32_t xb = sbase + (uint32_t)lane * QROW + (uint32_t)r * 16u;
        uint32_t tb = smb + TM_OFF + (uint32_t)((q * QCHUNKS + r) * 16);
        #pragma unroll 1
        for (int i = 0; i < niter; i++) {
            uint64_t x01[NGRP], x23[NGRP];
            XLOAD(0, "0"); XLOAD(1, "25088"); XLOAD(2, "50176"); XLOAD(3, "75264");
            KSTEP(0, "0");     KSTEP(1, "3136");  KSTEP(2, "6272");
            KSTEP(3, "9408");  KSTEP(4, "12544"); KSTEP(5, "15680");
            KSTEP(6, "18816"); KSTEP(7, "21952"); KSTEP(8, "25088");
            KSTEP(9, "28224");
            FMA2(acc[NTPL][0], x01[0], x01[0]); FMA2(acc[NTPL][0], x23[0], x23[0]);
            FMA2(acc[NTPL][1], x01[1], x01[1]); FMA2(acc[NTPL][1], x23[1], x23[1]);
            FMA2(acc[NTPL][2], x01[2], x01[2]); FMA2(acc[NTPL][2], x23[2], x23[2]);
            FMA2(acc[NTPL][3], x01[3], x01[3]); FMA2(acc[NTPL][3], x23[3], x23[3]);
            xb += (uint32_t)(NW * 16);
            tb += (uint32_t)(NW * 16);
        }
        __syncthreads();   // stage consumed

        if (q == 3) {
            // ---- epilogue in the dead stage (scratch) ----
            float* red = sm + (st ? (STAGE_BYTES >> 2) : 0);   // [k][w][img]
            #pragma unroll
            for (int k = 0; k < NACC; k++)
                #pragma unroll
                for (int g = 0; g < NGRP; g++) {
                    uint32_t lo, hi;
                    asm("mov.b64 {%0, %1}, %2;" : "=r"(lo), "=r"(hi) : "l"(acc[k][g]));
                    red[(k * NW + w) * TILE + g * 32 + lane] =
                        __uint_as_float(lo) + __uint_as_float(hi);
                }
            __syncthreads();

            double* xxd = (double*)((char*)red + XXD_OFF_E);   // [img]
            float* df = (float*)((char*)red + DF_OFF_E);       // [k][img]

            // Pass A: exact 16-way fold of x·x (k=10) via TwoSum -> fp64.
            if (tid < TILE) {
                const float* rp = red + NTPL * (NW * TILE) + tid;
                float fs = 0.f, fe = 0.f;
                #pragma unroll
                for (int ww = 0; ww < NW; ww++) {
                    const float v = rp[ww * TILE];
                    const float tt = fs + v;
                    const float z = tt - fs;
                    fe += (fs - (tt - z)) + (v - z);
                    fs = tt;
                }
                xxd[tid] = (double)fs + (double)fe;
            }
            __syncthreads();

            // Pass B: fold k=0..9 and form fp32-rounded distances in one step.
            for (int p = tid; p < NTPL * TILE; p += THREADS) {
                const int k = p >> 7, img = p & (TILE - 1);
                const float* rp = red + k * (NW * TILE) + img;
                float fs = 0.f, fe = 0.f;
                #pragma unroll
                for (int ww = 0; ww < NW; ww++) {
                    const float v = rp[ww * TILE];
                    const float tt = fs + v;
                    const float z = tt - fs;
                    fe += (fs - (tt - z)) + (v - z);
                    fs = tt;
                }
                const double c = (double)fs + (double)fe;
                df[p] = (float)((fma(-2.0, c, xxd[img]) + tsq_d[k]) * INV784);
            }
            __syncthreads();

            // argmin (strict <, first index wins ties == jnp.argmin).
            if (tid < TILE) {
                float best = df[tid];
                int bi = 0;
                #pragma unroll
                for (int kk = 1; kk < NTPL; kk++) {
                    const float v = df[kk * TILE + tid];
                    if (v < best) { best = v; bi = kk; }
                }
                out[(size_t)tile * TILE + tid] = (float)bi;
            }
            __syncthreads();
        }

        // Refill this stage with linear quarter j+2 (one TMA request).
        if (tid == 0 && j + 2 < nq) {
            const int j2 = j + 2;
            fetch_quarter(&tmap, t0 + (j2 >> 2) * G, j2 & 3, sbase, mbar);
        }
    }
}

typedef CUresult (*EncodeFn)(CUtensorMap*, CUtensorMapDataType, cuuint32_t, void*,
                             const cuuint64_t*, const cuuint64_t*, const cuuint32_t*,
                             const cuuint32_t*, CUtensorMapInterleave, CUtensorMapSwizzle,
                             CUtensorMapL2promotion, CUtensorMapFloatOOBfill);

extern "C" void kernel_launch(void* const* d_in, const int* in_sizes, int n_in,
                              void* d_out, int out_size) {
    // Robust to input ordering: x is the big one.
    const float* a = (const float*)d_in[0];
    const float* b = (const float*)d_in[1];
    const float* xg;
    const float* tg;
    long nx;
    if (in_sizes[0] >= in_sizes[1]) { xg = a; tg = b; nx = in_sizes[0]; }
    else                            { xg = b; tg = a; nx = in_sizes[1]; }

    const int B = (int)(nx / PIX);
    const int ntiles = B / TILE;   // 262144/128 = 2048, exact

    // Encode the x tensormap: [784 cols x B rows] fp32, box [196 x 128].
    static CUtensorMap tmap;       // persists across graph replays
    {
        EncodeFn enc = nullptr;
        cudaDriverEntryPointQueryResult qr = cudaDriverEntryPointSuccess;
        cudaError_t e = cudaGetDriverEntryPointByVersion(
            "cuTensorMapEncodeTiled", (void**)&enc, 12000, cudaEnableDefault, &qr);
        if (e != cudaSuccess || qr != cudaDriverEntryPointSuccess || enc == nullptr) {
            enc = nullptr;
            cudaGetDriverEntryPoint("cuTensorMapEncodeTiled", (void**)&enc,
                                    cudaEnableDefault, &qr);
        }
        if (enc != nullptr) {
            cuuint64_t gdims[2] = {(cuuint64_t)PIX, (cuuint64_t)B};
            cuuint64_t gstride[1] = {(cuuint64_t)IMG_BYTES};
            cuuint32_t box[2] = {(cuuint32_t)(QCHUNKS * 4), (cuuint32_t)TILE};
            cuuint32_t estride[2] = {1, 1};
            enc(&tmap, CU_TENSOR_MAP_DATA_TYPE_FLOAT32, 2, (void*)xg,
                gdims, gstride, box, estride,
                CU_TENSOR_MAP_INTERLEAVE_NONE, CU_TENSOR_MAP_SWIZZLE_NONE,
                CU_TENSOR_MAP_L2_PROMOTION_L2_128B, CU_TENSOR_MAP_FLOAT_OOB_FILL_NONE);
        }
    }

    int dev = 0;
    cudaGetDevice(&dev);
    int nsm = 148;
    cudaDeviceGetAttribute(&nsm, cudaDevAttrMultiProcessorCount, dev);
    int grid = nsm < ntiles ? nsm : ntiles;

    cudaFuncSetAttribute(mse_argmin_kernel,
                         cudaFuncAttributeMaxDynamicSharedMemorySize, SMEM_TOTAL);

    mse_argmin_kernel<<<grid, THREADS, SMEM_TOTAL>>>(tmap, tg, (float*)d_out, ntiles);
}